// round 15
// baseline (speedup 1.0000x reference)
#include <cuda_runtime.h>
#include <math.h>
#include <stdint.h>

// InstanceAwarePointMatching — 2 launches, max overlap:
//  Pass1 (3 block ranges, independent):
//    [zero ] coalesced uint4 zero-fill of both output maps (inline "memset")
//    [row  ] thread-per-(p,r) batched scan -> row top-3 table (4MB)
//    [col/2] thread-per-(p,s,half) batched scan -> partial top-4 scratch (8MB)
//  Pass2 (2 block ranges, after Pass1):
//    [rowSc] read row table, atomicAdd score + corr stores
//    [colMg] merge 2 halves, exp-rerank, atomicAdd score + corr stores
//
//   score = exp(msm) [P,R,S]; row top-3 along s; col top-3 along r.
//   score_map = 0.5*(ref+src); corr_map = (row_hit|col_hit) & refm & srcm.
// Masks arrive as 4-byte elements (uint32 != 0).
//
// Top-k exactness: top-4 on RAW scores ordered (v desc, idx asc); finalists
// re-ranked by (expf desc, idx asc); top-3 kept. Matches jax.lax.top_k over
// exp() including float32 exp-rounding ties. Scans ascend in index; >= batch
// prefilters are tie-exact. atomicAdd order (row half vs col half at an
// overlap cell) is commutative over the same two floats -> deterministic.

#define MAX_ROWS (1 << 18)       // >= P*R
#define MAX_COLH (1 << 19)       // >= 2*P*S

__device__ float4 g_rowE[MAX_ROWS];   // row top-3 exp values
__device__ int4   g_rowI[MAX_ROWS];   // row top-3 indices
__device__ float4 g_cv[MAX_COLH];     // col half partial top-4 raw values
__device__ int4   g_ci[MAX_COLH];     // col half partial top-4 indices

struct T4 { float v0, v1, v2, v3; int i0, i1, i2, i3; };

__device__ __forceinline__ bool better(float v, int i, float w, int j) {
    return (v > w) || (v == w && (unsigned)i < (unsigned)j);
}

__device__ __forceinline__ void t4_init(T4& t) {
    t.v0 = t.v1 = t.v2 = t.v3 = -INFINITY;
    t.i0 = t.i1 = t.i2 = t.i3 = 0x7FFFFFFF;
}

__device__ __forceinline__ void t4_insert(T4& t, float v, int i) {
    if (better(v, i, t.v3, t.i3)) {
        if (better(v, i, t.v2, t.i2)) {
            t.v3 = t.v2; t.i3 = t.i2;
            if (better(v, i, t.v1, t.i1)) {
                t.v2 = t.v1; t.i2 = t.i1;
                if (better(v, i, t.v0, t.i0)) {
                    t.v1 = t.v0; t.i1 = t.i0;
                    t.v0 = v; t.i0 = i;
                } else { t.v1 = v; t.i1 = i; }
            } else { t.v2 = v; t.i2 = i; }
        } else { t.v3 = v; t.i3 = i; }
    }
}

// Re-rank 4 raw finalists by (expf desc, idx asc); emit top-3.
__device__ __forceinline__ void finalize3(const T4& t, float* ev, int* ei) {
    float e[4] = { expf(t.v0), expf(t.v1), expf(t.v2), expf(t.v3) };
    int   x[4] = { t.i0, t.i1, t.i2, t.i3 };
    #pragma unroll
    for (int a = 1; a < 4; a++) {
        #pragma unroll
        for (int b = a; b > 0; b--) {
            if (better(e[b], x[b], e[b-1], x[b-1])) {
                float tv = e[b]; e[b] = e[b-1]; e[b-1] = tv;
                int   ti = x[b]; x[b] = x[b-1]; x[b-1] = ti;
            }
        }
    }
    ev[0] = e[0]; ev[1] = e[1]; ev[2] = e[2];
    ei[0] = x[0]; ei[1] = x[1]; ei[2] = x[2];
}

#define ZCHUNK 32   // uint4 per thread in the zero range

// ---------------------------------------------------------------------------
// Pass 1: [0,zeroB) zero-fill | [zeroB,zeroB+rowB) row scan | rest col halves
// ---------------------------------------------------------------------------
__global__ void __launch_bounds__(256)
pass1(const float* __restrict__ msm,
      uint4* __restrict__ out_u4, long long total_u4,
      int P, int R, int S, int zeroB, int rowB)
{
    const int bx  = (int)blockIdx.x;
    const int tid = threadIdx.x;

    if (bx < zeroB) {
        // ---- zero range: coalesced streaming zeros ----
        const uint4 z = make_uint4(0u, 0u, 0u, 0u);
        long long base = (long long)bx * (256 * ZCHUNK) + tid;
        #pragma unroll
        for (int k = 0; k < ZCHUNK; k++) {
            const long long i = base + (long long)k * 256;
            if (i < total_u4) out_u4[i] = z;
        }
        return;
    }

    if (bx < zeroB + rowB) {
        // ---- row scan: thread per (p,r), batches of 4 float4 ----
        const int row = (bx - zeroB) * 256 + tid;
        if (row >= P * R) return;

        const float4* __restrict__ rowp = (const float4*)(msm + (size_t)row * S);
        const int nj = S >> 2;

        T4 t; t4_init(t);
        int j = 0;
        for (; j + 4 <= nj; j += 4) {
            const float4 a = __ldg(rowp + j);
            const float4 b = __ldg(rowp + j + 1);
            const float4 c = __ldg(rowp + j + 2);
            const float4 d = __ldg(rowp + j + 3);
            const float m0 = fmaxf(fmaxf(a.x, a.y), fmaxf(a.z, a.w));
            const float m1 = fmaxf(fmaxf(b.x, b.y), fmaxf(b.z, b.w));
            const float m2 = fmaxf(fmaxf(c.x, c.y), fmaxf(c.z, c.w));
            const float m3 = fmaxf(fmaxf(d.x, d.y), fmaxf(d.z, d.w));
            const float mx = fmaxf(fmaxf(m0, m1), fmaxf(m2, m3));
            if (mx >= t.v3) {
                const int s0 = j << 2;
                t4_insert(t, a.x, s0);      t4_insert(t, a.y, s0 + 1);
                t4_insert(t, a.z, s0 + 2);  t4_insert(t, a.w, s0 + 3);
                t4_insert(t, b.x, s0 + 4);  t4_insert(t, b.y, s0 + 5);
                t4_insert(t, b.z, s0 + 6);  t4_insert(t, b.w, s0 + 7);
                t4_insert(t, c.x, s0 + 8);  t4_insert(t, c.y, s0 + 9);
                t4_insert(t, c.z, s0 + 10); t4_insert(t, c.w, s0 + 11);
                t4_insert(t, d.x, s0 + 12); t4_insert(t, d.y, s0 + 13);
                t4_insert(t, d.z, s0 + 14); t4_insert(t, d.w, s0 + 15);
            }
        }
        for (; j < nj; j++) {
            const float4 a = __ldg(rowp + j);
            const int s0 = j << 2;
            t4_insert(t, a.x, s0);     t4_insert(t, a.y, s0 + 1);
            t4_insert(t, a.z, s0 + 2); t4_insert(t, a.w, s0 + 3);
        }

        float ev[3]; int ei[3];
        finalize3(t, ev, ei);
        g_rowE[row] = make_float4(ev[0], ev[1], ev[2], 0.0f);
        g_rowI[row] = make_int4(ei[0], ei[1], ei[2], -1);
        return;
    }

    // ---- col halves: thread per (p,s,half), batches of 8 coalesced loads ----
    {
        const int PS = P * S;
        const int idx = (bx - zeroB - rowB) * 256 + tid;
        if (idx >= 2 * PS) return;
        const int h  = idx >= PS;
        const int ps = idx - h * PS;
        const int p  = ps / S;
        const int s  = ps - p * S;
        const int R2 = R >> 1;
        const int rlo = h ? R2 : 0;
        const int rhi = h ? R : R2;

        const float* __restrict__ base = msm + (size_t)p * R * S + s;

        T4 t; t4_init(t);
        int r0 = rlo;
        for (; r0 + 8 <= rhi; r0 += 8) {
            float v[8];
            #pragma unroll
            for (int k = 0; k < 8; k++) {
                v[k] = __ldg(base + (size_t)(r0 + k) * S);
            }
            const float m0 = fmaxf(fmaxf(v[0], v[1]), fmaxf(v[2], v[3]));
            const float m1 = fmaxf(fmaxf(v[4], v[5]), fmaxf(v[6], v[7]));
            const float mx = fmaxf(m0, m1);
            if (mx >= t.v3) {
                #pragma unroll
                for (int k = 0; k < 8; k++) {
                    t4_insert(t, v[k], r0 + k);
                }
            }
        }
        for (; r0 < rhi; r0++) {
            t4_insert(t, __ldg(base + (size_t)r0 * S), r0);
        }

        g_cv[idx] = make_float4(t.v0, t.v1, t.v2, t.v3);
        g_ci[idx] = make_int4(t.i0, t.i1, t.i2, t.i3);
    }
}

// ---------------------------------------------------------------------------
// Pass 2: [0,rowScB) row scatter | [rowScB, rowScB+colMgB) col merge+scatter
// ---------------------------------------------------------------------------
template <typename CorrT>
__global__ void __launch_bounds__(256)
pass2(const unsigned int* __restrict__ refm,
      const unsigned int* __restrict__ srcm,
      float* __restrict__ score_out,
      CorrT* __restrict__ corr_out,
      int P, int R, int S, int rowScB)
{
    const int bx  = (int)blockIdx.x;
    const int tid = threadIdx.x;

    if (bx < rowScB) {
        // ---- row scatter ----
        const int row = bx * 256 + tid;
        if (row >= P * R) return;
        const int p = row / R;

        const float4 e = g_rowE[row];
        const int4   i = g_rowI[row];
        const float ev[3] = { e.x, e.y, e.z };
        const int   ei[3] = { i.x, i.y, i.z };
        const bool rm = __ldg(refm + row) != 0u;
        #pragma unroll
        for (int k = 0; k < 3; k++) {
            const int s = ei[k];
            if ((unsigned)s < (unsigned)S) {
                atomicAdd(&score_out[(size_t)row * S + s], 0.5f * ev[k]);
                if (rm && __ldg(srcm + (size_t)p * S + s) != 0u) {
                    corr_out[(size_t)row * S + s] = (CorrT)1;
                }
            }
        }
        return;
    }

    // ---- col merge + scatter ----
    {
        const int PS = P * S;
        const int idx = (bx - rowScB) * 256 + tid;
        if (idx >= PS) return;
        const int p = idx / S;
        const int s = idx - p * S;

        T4 t; t4_init(t);
        #pragma unroll
        for (int h = 0; h < 2; h++) {
            const int q = h * PS + idx;
            const float4 v = g_cv[q];
            const int4   i = g_ci[q];
            t4_insert(t, v.x, i.x);
            t4_insert(t, v.y, i.y);
            t4_insert(t, v.z, i.z);
            t4_insert(t, v.w, i.w);
        }

        float ev[3]; int ei[3];
        finalize3(t, ev, ei);
        const bool sm = __ldg(srcm + idx) != 0u;
        #pragma unroll
        for (int k = 0; k < 3; k++) {
            const int r = ei[k];
            if ((unsigned)r < (unsigned)R) {
                atomicAdd(&score_out[((size_t)p * R + r) * S + s], 0.5f * ev[k]);
                if (sm && __ldg(refm + (size_t)p * R + r) != 0u) {
                    corr_out[((size_t)p * R + r) * S + s] = (CorrT)1;
                }
            }
        }
    }
}

extern "C" void kernel_launch(void* const* d_in, const int* in_sizes, int n_in,
                              void* d_out, int out_size)
{
    const float*        msm  = (const float*)d_in[0];
    // d_in[1] = node_corr_scores (unused: conditional=False)
    const unsigned int* refm = (const unsigned int*)d_in[2];   // bool -> 4-byte
    const unsigned int* srcm = (const unsigned int*)d_in[3];   // bool -> 4-byte

    const int P = in_sizes[1];
    const int R = in_sizes[2] / P;
    const int S = in_sizes[3] / P;
    const size_t N = (size_t)P * R * S;

    float* score_out = (float*)d_out;
    const int tpb = 256;

    const int rowB  = (P * R + tpb - 1) / tpb;           // row-scan blocks
    const int colB2 = (2 * P * S + tpb - 1) / tpb;       // col-half blocks
    const int rowScB = rowB;                             // row-scatter blocks
    const int colMgB = (P * S + tpb - 1) / tpb;          // col-merge blocks

    // total output bytes (both maps), zero-filled inside pass1
    const size_t out_bytes = ((size_t)out_size == 2 * N)
                           ? 2 * N * sizeof(float)
                           : N * sizeof(float) + N;
    const long long total_u4 = (long long)(out_bytes >> 4);
    const int zeroB = (int)((total_u4 + (long long)tpb * ZCHUNK - 1)
                            / ((long long)tpb * ZCHUNK));

    pass1<<<zeroB + rowB + colB2, tpb>>>(
        msm, (uint4*)d_out, total_u4, P, R, S, zeroB, rowB);

    if ((size_t)out_size == 2 * N) {
        float* corr_out = score_out + N;
        pass2<float><<<rowScB + colMgB, tpb>>>(
            refm, srcm, score_out, corr_out, P, R, S, rowScB);
    } else {
        unsigned char* corr_out = (unsigned char*)d_out + N * sizeof(float);
        pass2<unsigned char><<<rowScB + colMgB, tpb>>>(
            refm, srcm, score_out, corr_out, P, R, S, rowScB);
    }
}